// round 3
// baseline (speedup 1.0000x reference)
#include <cuda_runtime.h>
#include <cstdint>

// Problem constants
#define Bz 8
#define Tz 1024
#define Dz 1024
#define Qz 8
#define Kz 4096
#define dz 128
#define Mz (Bz*Tz)               // 8192 rows
#define OUT_ELEMS (Mz*Dz)        // 8388608
#define IDX_ELEMS (Mz*Qz)        // 65536

// Scratch (device globals: allocation-free rule)
__device__ float g_xn[(size_t)Mz*Dz];   // rmsnorm'd input, 32MB
__device__ float g_hc2[Qz*Kz];          // 0.5 * ||code||^2
__device__ int   g_idx[Mz*Qz];          // argmin indices

// ---- f32x2 packed-FMA helpers (sm_103a FFMA2) ----
static __device__ __forceinline__ void ffma2(unsigned long long& d,
                                             unsigned long long a,
                                             unsigned long long b){
    asm("fma.rn.f32x2 %0, %1, %2, %3;" : "=l"(d) : "l"(a), "l"(b), "l"(d));
}
static __device__ __forceinline__ float2 unpack2(unsigned long long v){
    unsigned lo, hi;
    asm("mov.b64 {%0, %1}, %2;" : "=r"(lo), "=r"(hi) : "l"(v));
    return make_float2(__uint_as_float(lo), __uint_as_float(hi));
}
static __device__ __forceinline__ void cp16(uint32_t s, const float* g){
    asm volatile("cp.async.cg.shared.global [%0], [%1], 16;" :: "r"(s), "l"(g));
}

// ---------------- Kernel 1: input rmsnorm ----------------
__global__ void rmsnorm_in_kernel(const float* __restrict__ x,
                                  const float* __restrict__ w){
    int m = blockIdx.x, t = threadIdx.x;
    float4 v = reinterpret_cast<const float4*>(x)[(size_t)m*256 + t];
    float ss = v.x*v.x + v.y*v.y + v.z*v.z + v.w*v.w;
    __shared__ float sred[8];
    __shared__ float s_scale;
    #pragma unroll
    for (int o = 16; o > 0; o >>= 1) ss += __shfl_xor_sync(0xffffffffu, ss, o);
    if ((t & 31) == 0) sred[t >> 5] = ss;
    __syncthreads();
    if (t < 8){
        float s2 = sred[t];
        #pragma unroll
        for (int o = 4; o > 0; o >>= 1) s2 += __shfl_xor_sync(0xffu, s2, o);
        if (t == 0){
            float mean = s2 * (1.0f/1024.0f) + 1e-5f;
            float r = rsqrtf(mean);
            r = r * (1.5f - 0.5f*mean*r*r);   // one Newton step
            s_scale = r;
        }
    }
    __syncthreads();
    float sc = s_scale;
    float4 wv = reinterpret_cast<const float4*>(w)[t];
    float4 o4 = make_float4(v.x*sc*wv.x, v.y*sc*wv.y, v.z*sc*wv.z, v.w*sc*wv.w);
    reinterpret_cast<float4*>(g_xn)[(size_t)m*256 + t] = o4;
}

// ---------------- Kernel 2: 0.5 * ||code||^2 ----------------
__global__ void hc2_kernel(const float* __restrict__ cb){
    int code = blockIdx.x*8 + (threadIdx.x >> 5);
    int lane = threadIdx.x & 31;
    float4 c = reinterpret_cast<const float4*>(cb)[(size_t)code*32 + lane];
    float s = c.x*c.x + c.y*c.y + c.z*c.z + c.w*c.w;
    #pragma unroll
    for (int o = 16; o > 0; o >>= 1) s += __shfl_xor_sync(0xffffffffu, s, o);
    if (lane == 0) g_hc2[code] = 0.5f*s;
}

// ---------------- Kernel 3: fused GEMM + argmin ----------------
// Inner-product microkernel packed along k (f32x2), cp.async double-buffered B.
// Tile 64 rows x 64 cols per chunk, microtile 4x4 per thread (rows ty+16i, cols tx+16j).
// score = 0.5*c2 - x.c   (same argmin as full d2)
#define SW 132                     // smem row stride in words (16B aligned, conflict-free)
#define AW (64*SW)
#define BW (64*SW)
#define SMEM_ARGMIN ((AW + 2*BW)*4)   // 101376 bytes

__global__ void __launch_bounds__(256)
argmin_kernel(const float* __restrict__ cb, float* __restrict__ tail){
    extern __shared__ float sm[];
    float* As  = sm;
    float* Bs0 = sm + AW;
    float* Bs1 = sm + AW + BW;

    int tid = threadIdx.x;
    int tx = tid & 15, ty = tid >> 4;
    int q  = blockIdx.y;
    int m0 = blockIdx.x * 64;

    const float* xq  = g_xn + (size_t)m0*Dz + q*dz;     // row stride Dz, 128 floats used
    const float* cbq = cb + (size_t)q*Kz*dz;            // k-contiguous rows of 128
    const float* hcq = g_hc2 + q*Kz;

    uint32_t sA  = (uint32_t)__cvta_generic_to_shared(As);
    uint32_t sB0 = (uint32_t)__cvta_generic_to_shared(Bs0);
    uint32_t sB1 = (uint32_t)__cvta_generic_to_shared(Bs1);

    // A tile: 64 rows x 128 k, k-contiguous in smem (no transpose needed).
    #pragma unroll
    for (int it = 0; it < 8; ++it){
        int u = it*256 + tid;
        int row = u >> 5, ks = u & 31;                  // ks = 16B segment along k
        cp16(sA + (uint32_t)(row*SW + ks*4)*4u, xq + (size_t)row*Dz + ks*4);
    }
    // B chunk 0
    #pragma unroll
    for (int it = 0; it < 8; ++it){
        int u = it*256 + tid;
        int col = u >> 5, ks = u & 31;
        cp16(sB0 + (uint32_t)(col*SW + ks*4)*4u, cbq + (size_t)col*dz + ks*4);
    }
    asm volatile("cp.async.commit_group;");

    float bestv[4] = {3.4e38f, 3.4e38f, 3.4e38f, 3.4e38f};
    int   besti[4] = {0,0,0,0};

    for (int c = 0; c < 64; ++c){
        // Prefetch next B chunk into the other buffer
        if (c + 1 < 64){
            uint32_t sBn = ((c+1) & 1) ? sB1 : sB0;
            const float* bg = cbq + (size_t)(c+1)*64*dz;
            #pragma unroll
            for (int it = 0; it < 8; ++it){
                int u = it*256 + tid;
                int col = u >> 5, ks = u & 31;
                cp16(sBn + (uint32_t)(col*SW + ks*4)*4u, bg + (size_t)col*dz + ks*4);
            }
            asm volatile("cp.async.commit_group;");
            asm volatile("cp.async.wait_group 1;");
        } else {
            asm volatile("cp.async.wait_group 0;");
        }
        __syncthreads();

        const float* Bc = (c & 1) ? Bs1 : Bs0;
        const float* Ab = As + ty*SW;
        const float* Bb = Bc + tx*SW;

        unsigned long long acc[4][4];
        #pragma unroll
        for (int i = 0; i < 4; ++i)
            #pragma unroll
            for (int j = 0; j < 4; ++j) acc[i][j] = 0ull;

        #pragma unroll 2
        for (int k = 0; k < 128; k += 4){
            ulonglong2 a[4], b[4];
            #pragma unroll
            for (int i = 0; i < 4; ++i)
                a[i] = *reinterpret_cast<const ulonglong2*>(Ab + i*16*SW + k);
            #pragma unroll
            for (int j = 0; j < 4; ++j)
                b[j] = *reinterpret_cast<const ulonglong2*>(Bb + j*16*SW + k);
            #pragma unroll
            for (int i = 0; i < 4; ++i)
                #pragma unroll
                for (int j = 0; j < 4; ++j){
                    ffma2(acc[i][j], a[i].x, b[j].x);
                    ffma2(acc[i][j], a[i].y, b[j].y);
                }
        }

        // Fused epilogue: horizontal add + running min of (0.5*c2 - xc)
        int n0 = c*64;
        #pragma unroll
        for (int j = 0; j < 4; ++j){
            int n = n0 + tx + 16*j;
            float hc = __ldg(hcq + n);
            #pragma unroll
            for (int i = 0; i < 4; ++i){
                float2 p = unpack2(acc[i][j]);
                float s = hc - (p.x + p.y);
                if (s < bestv[i]) { bestv[i] = s; besti[i] = n; }
            }
        }
        __syncthreads();   // buffer (c&1) free for reuse at iteration c+2
    }

    // Cross-thread reduction per row (16 tx lanes), tie -> lower idx
    float* rv = sm;                                   // reuse smem: 64*16 floats
    int*   ri = reinterpret_cast<int*>(sm + 64*16);   // 64*16 ints
    #pragma unroll
    for (int i = 0; i < 4; ++i){
        int row = ty + 16*i;
        rv[row*16 + tx] = bestv[i];
        ri[row*16 + tx] = besti[i];
    }
    __syncthreads();
    if (tid < 64){
        float bv = rv[tid*16]; int bi = ri[tid*16];
        #pragma unroll
        for (int t2 = 1; t2 < 16; ++t2){
            float v = rv[tid*16 + t2]; int id = ri[tid*16 + t2];
            if (v < bv || (v == bv && id < bi)) { bv = v; bi = id; }
        }
        int m = m0 + tid;
        g_idx[m*Qz + q] = bi;
        if (tail) tail[m*Qz + q] = (float)bi;
    }
}

// ---------------- Kernel 4: gather codes + output rmsnorm ----------------
__global__ void out_kernel(const float* __restrict__ cb,
                           const float* __restrict__ w,
                           float* __restrict__ out){
    int m = blockIdx.x, t = threadIdx.x;
    __shared__ int   sidx[8];
    __shared__ float s_scale;
    if (t < 8) sidx[t] = g_idx[m*Qz + t];
    __syncthreads();
    if (t < 8){
        // sum of quant^2 over the row = sum_q 2*hc2[q][idx_q]
        float p = g_hc2[t*Kz + sidx[t]];
        #pragma unroll
        for (int o = 4; o > 0; o >>= 1) p += __shfl_xor_sync(0xffu, p, o);
        if (t == 0){
            float mean = (2.0f*p) * (1.0f/1024.0f) + 1e-5f;
            float r = rsqrtf(mean);
            r = r * (1.5f - 0.5f*mean*r*r);
            s_scale = r;
        }
    }
    __syncthreads();
    int q = t >> 5, lane = t & 31;
    float4 c = reinterpret_cast<const float4*>(cb)[((size_t)q*Kz + sidx[q])*32 + lane];
    float sc = s_scale;
    float4 wv = reinterpret_cast<const float4*>(w)[t];
    reinterpret_cast<float4*>(out)[(size_t)m*256 + t] =
        make_float4(c.x*sc*wv.x, c.y*sc*wv.y, c.z*sc*wv.z, c.w*sc*wv.w);
}

// ---------------- Launch ----------------
extern "C" void kernel_launch(void* const* d_in, const int* in_sizes, int n_in,
                              void* d_out, int out_size){
    const float* x     = (const float*)d_in[0];
    const float* cb    = (const float*)d_in[1];
    const float* w_in  = (const float*)d_in[2];
    const float* w_out = (const float*)d_in[3];
    float* out = (float*)d_out;
    float* tail = (out_size >= OUT_ELEMS + IDX_ELEMS) ? (out + OUT_ELEMS) : nullptr;

    cudaFuncSetAttribute((const void*)argmin_kernel,
                         cudaFuncAttributeMaxDynamicSharedMemorySize, SMEM_ARGMIN);

    rmsnorm_in_kernel<<<Mz, 256>>>(x, w_in);
    hc2_kernel<<<(Qz*Kz)/8, 256>>>(cb);
    argmin_kernel<<<dim3(Mz/64, Qz), 256, SMEM_ARGMIN>>>(cb, tail);
    out_kernel<<<Mz, 256>>>(cb, w_out, out);
}

// round 4
// speedup vs baseline: 1.3498x; 1.3498x over previous
#include <cuda_runtime.h>
#include <cstdint>

// Problem constants
#define Bz 8
#define Tz 1024
#define Dz 1024
#define Qz 8
#define Kz 4096
#define dz 128
#define Mz (Bz*Tz)               // 8192 rows
#define OUT_ELEMS (Mz*Dz)        // 8388608
#define IDX_ELEMS (Mz*Qz)        // 65536

// Scratch (device globals: allocation-free rule)
__device__ float g_xn[(size_t)Mz*Dz];   // rmsnorm'd input, 32MB
__device__ float g_hc2[Qz*Kz];          // 0.5 * ||code||^2
__device__ int   g_idx[Mz*Qz];          // argmin indices

// ---- f32x2 packed-FMA helpers (sm_103a FFMA2) ----
static __device__ __forceinline__ unsigned long long pack2(float v){
    unsigned long long r; unsigned u = __float_as_uint(v);
    asm("mov.b64 %0, {%1, %1};" : "=l"(r) : "r"(u));
    return r;
}
static __device__ __forceinline__ void ffma2(unsigned long long& d,
                                             unsigned long long a,
                                             unsigned long long b){
    asm("fma.rn.f32x2 %0, %1, %2, %0;" : "+l"(d) : "l"(a), "l"(b));
}
static __device__ __forceinline__ float2 unpack2(unsigned long long v){
    unsigned lo, hi;
    asm("mov.b64 {%0, %1}, %2;" : "=r"(lo), "=r"(hi) : "l"(v));
    return make_float2(__uint_as_float(lo), __uint_as_float(hi));
}

// ---------------- Kernel 1: input rmsnorm ----------------
__global__ void rmsnorm_in_kernel(const float* __restrict__ x,
                                  const float* __restrict__ w){
    int m = blockIdx.x, t = threadIdx.x;
    float4 v = reinterpret_cast<const float4*>(x)[(size_t)m*256 + t];
    float ss = v.x*v.x + v.y*v.y + v.z*v.z + v.w*v.w;
    __shared__ float sred[8];
    __shared__ float s_scale;
    #pragma unroll
    for (int o = 16; o > 0; o >>= 1) ss += __shfl_xor_sync(0xffffffffu, ss, o);
    if ((t & 31) == 0) sred[t >> 5] = ss;
    __syncthreads();
    if (t < 8){
        float s2 = sred[t];
        #pragma unroll
        for (int o = 4; o > 0; o >>= 1) s2 += __shfl_xor_sync(0xffu, s2, o);
        if (t == 0){
            float mean = s2 * (1.0f/1024.0f) + 1e-5f;
            float r = rsqrtf(mean);
            r = r * (1.5f - 0.5f*mean*r*r);   // one Newton step
            s_scale = r;
        }
    }
    __syncthreads();
    float sc = s_scale;
    float4 wv = reinterpret_cast<const float4*>(w)[t];
    float4 o4 = make_float4(v.x*sc*wv.x, v.y*sc*wv.y, v.z*sc*wv.z, v.w*sc*wv.w);
    reinterpret_cast<float4*>(g_xn)[(size_t)m*256 + t] = o4;
}

// ---------------- Kernel 2: 0.5 * ||code||^2 ----------------
__global__ void hc2_kernel(const float* __restrict__ cb){
    int code = blockIdx.x*8 + (threadIdx.x >> 5);
    int lane = threadIdx.x & 31;
    float4 c = reinterpret_cast<const float4*>(cb)[(size_t)code*32 + lane];
    float s = c.x*c.x + c.y*c.y + c.z*c.z + c.w*c.w;
    #pragma unroll
    for (int o = 16; o > 0; o >>= 1) s += __shfl_xor_sync(0xffffffffu, s, o);
    if (lane == 0) g_hc2[code] = 0.5f*s;
}

// ---------------- Kernel 3: fused GEMM + argmax(xc - 0.5c2) ----------------
// Outer-product 8x8 microtile in f32x2. A resident full-k in smem (transposed,
// broadcast-friendly). B double-buffered 128-col x 16-k tiles, reg-staged loads.
#define SA   132                   // As row-dim stride (words); STS conflict-free
#define BSTR 192                   // B k-row stride (words); 16 groups * 12
#define SMEM_ARGMIN (128*SA*4 + 2*16*BSTR*4)   // 67584 + 24576 = 92160

static __device__ __forceinline__ int bcol(int c){ return 12*(c>>3) + (c&7); }

__global__ void __launch_bounds__(256, 2)
argmin_kernel(const float* __restrict__ cb, float* __restrict__ tail){
    extern __shared__ float sm[];
    float* As = sm;
    float* B0 = sm + 128*SA;
    float* B1 = B0 + 16*BSTR;

    int tid = threadIdx.x;
    int tx = tid & 15, ty = tid >> 4;
    int q  = blockIdx.y;
    int m0 = blockIdx.x * 128;

    const float* xq  = g_xn + (size_t)m0*Dz + q*dz;
    const float* cbq = cb + (size_t)q*Kz*dz;
    const float* hcq = g_hc2 + q*Kz;

    // ---- A tile: 128 rows x 128 k, transposed As[k][row]. One-time load.
    // lanes run along k (coalesced LDG.32); STS.128 conflict-free (4(k+rg)+i fills banks)
    #pragma unroll
    for (int it = 0; it < 16; ++it){
        int u  = it*256 + tid;
        int kk = (u & 31) + ((u >> 10) << 5);
        int rg = (u >> 5) & 31;
        const float* p = xq + (size_t)(4*rg)*Dz + kk;
        float a0 = p[0], a1 = p[Dz], a2 = p[2*Dz], a3 = p[3*Dz];
        *reinterpret_cast<float4*>(&As[kk*SA + 4*rg]) = make_float4(a0,a1,a2,a3);
    }

    // per-thread B staging: 2 float4 per iteration (128 cols x 16 k / 256 thr)
    int pks0 = tid & 3,         pcol0 = tid >> 2;
    int pks1 = (256+tid) & 3,   pcol1 = (256+tid) >> 2;
    int bc0 = bcol(pcol0), bc1 = bcol(pcol1);

    // prologue: load + store B for iteration 0 into B0
    float4 pre0 = *reinterpret_cast<const float4*>(cbq + (size_t)pcol0*dz + 4*pks0);
    float4 pre1 = *reinterpret_cast<const float4*>(cbq + (size_t)pcol1*dz + 4*pks1);
    B0[(4*pks0+0)*BSTR + bc0] = pre0.x;  B0[(4*pks0+1)*BSTR + bc0] = pre0.y;
    B0[(4*pks0+2)*BSTR + bc0] = pre0.z;  B0[(4*pks0+3)*BSTR + bc0] = pre0.w;
    B0[(4*pks1+0)*BSTR + bc1] = pre1.x;  B0[(4*pks1+1)*BSTR + bc1] = pre1.y;
    B0[(4*pks1+2)*BSTR + bc1] = pre1.z;  B0[(4*pks1+3)*BSTR + bc1] = pre1.w;
    __syncthreads();

    unsigned long long acc[4][8];    // [row-pair][col]; rows 8*ty+2p, 8*ty+2p+1
    float bestv[8];
    int   besti[8];
    #pragma unroll
    for (int i = 0; i < 8; ++i){ bestv[i] = -3.4e38f; besti[i] = 0; }

    for (int it = 0; it < 256; ++it){           // it = chunk*8 + kc
        int c = it >> 3, kc = it & 7;

        // prefetch next B sub-tile into registers (hidden under compute)
        if (it + 1 < 256){
            int nc = (it+1) >> 3, nkc = (it+1) & 7;
            const float* bg = cbq + (size_t)nc*128*dz + nkc*16;
            pre0 = *reinterpret_cast<const float4*>(bg + (size_t)pcol0*dz + 4*pks0);
            pre1 = *reinterpret_cast<const float4*>(bg + (size_t)pcol1*dz + 4*pks1);
        }

        // chunk start: acc <- -0.5*||c||^2 (argmax form, no epilogue subtract)
        if (kc == 0){
            float4 h0 = *reinterpret_cast<const float4*>(hcq + c*128 + 8*tx);
            float4 h1 = *reinterpret_cast<const float4*>(hcq + c*128 + 8*tx + 4);
            unsigned long long hp[8];
            hp[0]=pack2(-h0.x); hp[1]=pack2(-h0.y); hp[2]=pack2(-h0.z); hp[3]=pack2(-h0.w);
            hp[4]=pack2(-h1.x); hp[5]=pack2(-h1.y); hp[6]=pack2(-h1.z); hp[7]=pack2(-h1.w);
            #pragma unroll
            for (int p = 0; p < 4; ++p)
                #pragma unroll
                for (int j = 0; j < 8; ++j) acc[p][j] = hp[j];
        }

        const float* Bc = (it & 1) ? B1 : B0;
        const float* Ab = As + (kc*16)*SA + 8*ty;
        const float* Bb = Bc + 12*tx;

        #pragma unroll
        for (int k = 0; k < 16; ++k){
            ulonglong2 a0 = *reinterpret_cast<const ulonglong2*>(Ab + k*SA);      // rows 0-3
            ulonglong2 a1 = *reinterpret_cast<const ulonglong2*>(Ab + k*SA + 4);  // rows 4-7
            float4 b0 = *reinterpret_cast<const float4*>(Bb + k*BSTR);
            float4 b1 = *reinterpret_cast<const float4*>(Bb + k*BSTR + 4);
            unsigned long long bb0 = pack2(b0.x), bb1 = pack2(b0.y);
            unsigned long long bb2 = pack2(b0.z), bb3 = pack2(b0.w);
            unsigned long long bb4 = pack2(b1.x), bb5 = pack2(b1.y);
            unsigned long long bb6 = pack2(b1.z), bb7 = pack2(b1.w);
            ffma2(acc[0][0], a0.x, bb0); ffma2(acc[1][0], a0.y, bb0);
            ffma2(acc[2][0], a1.x, bb0); ffma2(acc[3][0], a1.y, bb0);
            ffma2(acc[0][1], a0.x, bb1); ffma2(acc[1][1], a0.y, bb1);
            ffma2(acc[2][1], a1.x, bb1); ffma2(acc[3][1], a1.y, bb1);
            ffma2(acc[0][2], a0.x, bb2); ffma2(acc[1][2], a0.y, bb2);
            ffma2(acc[2][2], a1.x, bb2); ffma2(acc[3][2], a1.y, bb2);
            ffma2(acc[0][3], a0.x, bb3); ffma2(acc[1][3], a0.y, bb3);
            ffma2(acc[2][3], a1.x, bb3); ffma2(acc[3][3], a1.y, bb3);
            ffma2(acc[0][4], a0.x, bb4); ffma2(acc[1][4], a0.y, bb4);
            ffma2(acc[2][4], a1.x, bb4); ffma2(acc[3][4], a1.y, bb4);
            ffma2(acc[0][5], a0.x, bb5); ffma2(acc[1][5], a0.y, bb5);
            ffma2(acc[2][5], a1.x, bb5); ffma2(acc[3][5], a1.y, bb5);
            ffma2(acc[0][6], a0.x, bb6); ffma2(acc[1][6], a0.y, bb6);
            ffma2(acc[2][6], a1.x, bb6); ffma2(acc[3][6], a1.y, bb6);
            ffma2(acc[0][7], a0.x, bb7); ffma2(acc[1][7], a0.y, bb7);
            ffma2(acc[2][7], a1.x, bb7); ffma2(acc[3][7], a1.y, bb7);
        }

        // drain staged regs into the other buffer (its prior contents were
        // consumed last iteration; everyone synced since)
        if (it + 1 < 256){
            float* Bn = ((it+1) & 1) ? B1 : B0;
            Bn[(4*pks0+0)*BSTR + bc0] = pre0.x;  Bn[(4*pks0+1)*BSTR + bc0] = pre0.y;
            Bn[(4*pks0+2)*BSTR + bc0] = pre0.z;  Bn[(4*pks0+3)*BSTR + bc0] = pre0.w;
            Bn[(4*pks1+0)*BSTR + bc1] = pre1.x;  Bn[(4*pks1+1)*BSTR + bc1] = pre1.y;
            Bn[(4*pks1+2)*BSTR + bc1] = pre1.z;  Bn[(4*pks1+3)*BSTR + bc1] = pre1.w;
        }

        // chunk end: fold acc into running argmax (strict > keeps lowest idx)
        if (kc == 7){
            int n0 = c*128 + 8*tx;
            #pragma unroll
            for (int p = 0; p < 4; ++p)
                #pragma unroll
                for (int j = 0; j < 8; ++j){
                    float2 v = unpack2(acc[p][j]);
                    if (v.x > bestv[2*p])   { bestv[2*p]   = v.x; besti[2*p]   = n0 + j; }
                    if (v.y > bestv[2*p+1]) { bestv[2*p+1] = v.y; besti[2*p+1] = n0 + j; }
                }
        }
        __syncthreads();
    }

    // Cross-thread reduction: 16 tx candidates per row; max, tie -> lower idx
    float* rv = sm;                                    // 128*16 floats
    int*   ri = reinterpret_cast<int*>(sm + 128*16);   // 128*16 ints
    #pragma unroll
    for (int i = 0; i < 8; ++i){
        int row = 8*ty + i;
        rv[row*16 + tx] = bestv[i];
        ri[row*16 + tx] = besti[i];
    }
    __syncthreads();
    if (tid < 128){
        float bv = rv[tid*16]; int bi = ri[tid*16];
        #pragma unroll
        for (int t2 = 1; t2 < 16; ++t2){
            float v = rv[tid*16 + t2]; int id = ri[tid*16 + t2];
            if (v > bv || (v == bv && id < bi)) { bv = v; bi = id; }
        }
        int m = m0 + tid;
        g_idx[m*Qz + q] = bi;
        if (tail) tail[m*Qz + q] = (float)bi;
    }
}

// ---------------- Kernel 4: gather codes + output rmsnorm ----------------
__global__ void out_kernel(const float* __restrict__ cb,
                           const float* __restrict__ w,
                           float* __restrict__ out){
    int m = blockIdx.x, t = threadIdx.x;
    __shared__ int   sidx[8];
    __shared__ float s_scale;
    if (t < 8) sidx[t] = g_idx[m*Qz + t];
    __syncthreads();
    if (t < 8){
        float p = g_hc2[t*Kz + sidx[t]];
        #pragma unroll
        for (int o = 4; o > 0; o >>= 1) p += __shfl_xor_sync(0xffu, p, o);
        if (t == 0){
            float mean = (2.0f*p) * (1.0f/1024.0f) + 1e-5f;
            float r = rsqrtf(mean);
            r = r * (1.5f - 0.5f*mean*r*r);
            s_scale = r;
        }
    }
    __syncthreads();
    int q = t >> 5, lane = t & 31;
    float4 c = reinterpret_cast<const float4*>(cb)[((size_t)q*Kz + sidx[q])*32 + lane];
    float sc = s_scale;
    float4 wv = reinterpret_cast<const float4*>(w)[t];
    reinterpret_cast<float4*>(out)[(size_t)m*256 + t] =
        make_float4(c.x*sc*wv.x, c.y*sc*wv.y, c.z*sc*wv.z, c.w*sc*wv.w);
}

// ---------------- Launch ----------------
extern "C" void kernel_launch(void* const* d_in, const int* in_sizes, int n_in,
                              void* d_out, int out_size){
    const float* x     = (const float*)d_in[0];
    const float* cb    = (const float*)d_in[1];
    const float* w_in  = (const float*)d_in[2];
    const float* w_out = (const float*)d_in[3];
    float* out = (float*)d_out;
    float* tail = (out_size >= OUT_ELEMS + IDX_ELEMS) ? (out + OUT_ELEMS) : nullptr;

    cudaFuncSetAttribute((const void*)argmin_kernel,
                         cudaFuncAttributeMaxDynamicSharedMemorySize, SMEM_ARGMIN);

    rmsnorm_in_kernel<<<Mz, 256>>>(x, w_in);
    hc2_kernel<<<(Qz*Kz)/8, 256>>>(cb);
    argmin_kernel<<<dim3(Mz/128, Qz), 256, SMEM_ARGMIN>>>(cb, tail);
    out_kernel<<<Mz, 256>>>(cb, w_out, out);
}